// round 11
// baseline (speedup 1.0000x reference)
#include <cuda_runtime.h>
#include <stdint.h>

// BFP quantizer: x (64, 256, 56, 56) fp32 NCHW, tile=8 along C (axis 1).
// bitwidth=16 -> m=7, qmax=127, step=2^(shared_exp-6).
// shared_exp = floor(log2(max(|x| over tile), eps)), eps=2^-23.
//
// FINAL. 4 good-state reproductions: 56.70 / 56.96 / 57.09 / 57.38 us
// kernel, DRAM 78.4-79.3% (6.2-6.3 TB/s) on a 50/50 r/w stream — within
// ~1.5% of the mixed-stream HBM floor (411 MB mandatory traffic / ~79%
// controller efficiency ~= 56.5us). Sweep findings (8 configs):
//   - warp-dense vector accesses mandatory (strided pairs: -36%, real)
//   - flat launch > persistent grid-stride (-6%, real)
//   - __ldcs/__stcs >= default > __stwt (-3%)
//   - occupancy 20-60%, MLP 8-16, block 256/512: within noise
//   - TMA / striding / traffic reduction ruled out by the B300 HW model
//
// Thread = (n, c_tile, w), covers float4 positions w and w+392 across all
// 8 channels of the tile: 16 front-batched streaming LDG.128, each with
// warp lanes at consecutive 16B (fully dense wavefronts).
// Exact math: shared_exp via IEEE exponent bits (maxabs clamped to eps is
// always normal), rintf = round-half-even, step/inv_step bit-constructed
// powers of two (exponents always in normal range). rel_err = 0.0.

#define N_DIM   64
#define C_DIM   256
#define HW_DIM  3136               // 56*56
#define TILE_C  8
#define NTILES  (C_DIM / TILE_C)   // 32
#define HW4     (HW_DIM / 4)       // 784
#define HW8     (HW4 / 2)          // 392
#define EPS_F   1.1920928955078125e-07f  // 2^-23

__global__ __launch_bounds__(256, 2)
void bfp_quant_kernel(const float4* __restrict__ in, float4* __restrict__ out)
{
    int t = blockIdx.x * blockDim.x + threadIdx.x;
    // t in [0, N*NTILES*HW8)
    int w    = t % HW8;
    int rest = t / HW8;
    int ct   = rest % NTILES;
    int n    = rest / NTILES;

    long base = (long)n * (C_DIM * HW4) + (long)ct * (TILE_C * HW4) + w;

    // Front-batched: 16 streaming LDG.128
    float a[TILE_C][2][4];
    #pragma unroll
    for (int k = 0; k < TILE_C; k++) {
        float4 v0 = __ldcs(&in[base + (long)k * HW4]);
        float4 v1 = __ldcs(&in[base + (long)k * HW4 + HW8]);
        a[k][0][0] = v0.x; a[k][0][1] = v0.y; a[k][0][2] = v0.z; a[k][0][3] = v0.w;
        a[k][1][0] = v1.x; a[k][1][1] = v1.y; a[k][1][2] = v1.z; a[k][1][3] = v1.w;
    }

    #pragma unroll
    for (int g = 0; g < 2; g++) {
        #pragma unroll
        for (int j = 0; j < 4; j++) {
            // tile max(|x|) clamped by eps
            float mx = EPS_F;
            #pragma unroll
            for (int k = 0; k < TILE_C; k++)
                mx = fmaxf(mx, fabsf(a[k][g][j]));

            // shared_exp = floor(log2(mx)): exponent bits (mx normal, >0)
            int e = (int)(__float_as_uint(mx) >> 23) - 127;

            // inv_step = 2^(6-e), step = 2^(e-6), both always normal
            float inv_step = __uint_as_float((uint32_t)(133 - e) << 23);
            float step     = __uint_as_float((uint32_t)(e + 121) << 23);

            #pragma unroll
            for (int k = 0; k < TILE_C; k++) {
                float q = rintf(a[k][g][j] * inv_step);   // round-half-even
                q = fminf(fmaxf(q, -127.0f), 127.0f);
                a[k][g][j] = q * step;
            }
        }
    }

    #pragma unroll
    for (int k = 0; k < TILE_C; k++) {
        float4 v0, v1;
        v0.x = a[k][0][0]; v0.y = a[k][0][1]; v0.z = a[k][0][2]; v0.w = a[k][0][3];
        v1.x = a[k][1][0]; v1.y = a[k][1][1]; v1.z = a[k][1][2]; v1.w = a[k][1][3];
        __stcs(&out[base + (long)k * HW4], v0);
        __stcs(&out[base + (long)k * HW4 + HW8], v1);
    }
}

extern "C" void kernel_launch(void* const* d_in, const int* in_sizes, int n_in,
                              void* d_out, int out_size)
{
    const float4* in  = (const float4*)d_in[0];
    float4*       out = (float4*)d_out;

    const int total_threads = N_DIM * NTILES * HW8;   // 802,816
    const int block = 256;
    const int grid  = total_threads / block;          // 3136 exactly

    bfp_quant_kernel<<<grid, block>>>(in, out);
}

// round 12
// speedup vs baseline: 1.0085x; 1.0085x over previous
#include <cuda_runtime.h>
#include <stdint.h>

// BFP quantizer: x (64, 256, 56, 56) fp32 NCHW, tile=8 along C (axis 1).
// bitwidth=16 -> m=7, qmax=127, step=2^(shared_exp-6).
// shared_exp = floor(log2(max(|x| over tile), eps)), eps=2^-23.
//
// FINAL. 5 good-state reproductions: 56.70 / 56.96 / 57.09 / 57.38 / 57.38
// us kernel, DRAM 78.2-79.3% (6.2-6.3 TB/s) on a 50/50 r/w stream — within
// ~1.5% of the mixed-stream HBM floor (411 MB mandatory traffic / ~79%
// controller efficiency ~= 56.5us). Sweep findings (8 configs):
//   - warp-dense vector accesses mandatory (strided pairs: -36%, real)
//   - flat launch > persistent grid-stride (-6%, real)
//   - __ldcs/__stcs >= default > __stwt (-3%)
//   - occupancy 20-60%, MLP 8-16, block 256/512: within noise
//   - TMA / striding / traffic reduction ruled out by the B300 HW model
//
// Thread = (n, c_tile, w), covers float4 positions w and w+392 across all
// 8 channels of the tile: 16 front-batched streaming LDG.128, each with
// warp lanes at consecutive 16B (fully dense wavefronts).
// Exact math: shared_exp via IEEE exponent bits (maxabs clamped to eps is
// always normal), rintf = round-half-even, step/inv_step bit-constructed
// powers of two (exponents always in normal range). rel_err = 0.0.

#define N_DIM   64
#define C_DIM   256
#define HW_DIM  3136               // 56*56
#define TILE_C  8
#define NTILES  (C_DIM / TILE_C)   // 32
#define HW4     (HW_DIM / 4)       // 784
#define HW8     (HW4 / 2)          // 392
#define EPS_F   1.1920928955078125e-07f  // 2^-23

__global__ __launch_bounds__(256, 2)
void bfp_quant_kernel(const float4* __restrict__ in, float4* __restrict__ out)
{
    int t = blockIdx.x * blockDim.x + threadIdx.x;
    // t in [0, N*NTILES*HW8)
    int w    = t % HW8;
    int rest = t / HW8;
    int ct   = rest % NTILES;
    int n    = rest / NTILES;

    long base = (long)n * (C_DIM * HW4) + (long)ct * (TILE_C * HW4) + w;

    // Front-batched: 16 streaming LDG.128
    float a[TILE_C][2][4];
    #pragma unroll
    for (int k = 0; k < TILE_C; k++) {
        float4 v0 = __ldcs(&in[base + (long)k * HW4]);
        float4 v1 = __ldcs(&in[base + (long)k * HW4 + HW8]);
        a[k][0][0] = v0.x; a[k][0][1] = v0.y; a[k][0][2] = v0.z; a[k][0][3] = v0.w;
        a[k][1][0] = v1.x; a[k][1][1] = v1.y; a[k][1][2] = v1.z; a[k][1][3] = v1.w;
    }

    #pragma unroll
    for (int g = 0; g < 2; g++) {
        #pragma unroll
        for (int j = 0; j < 4; j++) {
            // tile max(|x|) clamped by eps
            float mx = EPS_F;
            #pragma unroll
            for (int k = 0; k < TILE_C; k++)
                mx = fmaxf(mx, fabsf(a[k][g][j]));

            // shared_exp = floor(log2(mx)): exponent bits (mx normal, >0)
            int e = (int)(__float_as_uint(mx) >> 23) - 127;

            // inv_step = 2^(6-e), step = 2^(e-6), both always normal
            float inv_step = __uint_as_float((uint32_t)(133 - e) << 23);
            float step     = __uint_as_float((uint32_t)(e + 121) << 23);

            #pragma unroll
            for (int k = 0; k < TILE_C; k++) {
                float q = rintf(a[k][g][j] * inv_step);   // round-half-even
                q = fminf(fmaxf(q, -127.0f), 127.0f);
                a[k][g][j] = q * step;
            }
        }
    }

    #pragma unroll
    for (int k = 0; k < TILE_C; k++) {
        float4 v0, v1;
        v0.x = a[k][0][0]; v0.y = a[k][0][1]; v0.z = a[k][0][2]; v0.w = a[k][0][3];
        v1.x = a[k][1][0]; v1.y = a[k][1][1]; v1.z = a[k][1][2]; v1.w = a[k][1][3];
        __stcs(&out[base + (long)k * HW4], v0);
        __stcs(&out[base + (long)k * HW4 + HW8], v1);
    }
}

extern "C" void kernel_launch(void* const* d_in, const int* in_sizes, int n_in,
                              void* d_out, int out_size)
{
    const float4* in  = (const float4*)d_in[0];
    float4*       out = (float4*)d_out;

    const int total_threads = N_DIM * NTILES * HW8;   // 802,816
    const int block = 256;
    const int grid  = total_threads / block;          // 3136 exactly

    bfp_quant_kernel<<<grid, block>>>(in, out);
}